// round 6
// baseline (speedup 1.0000x reference)
#include <cuda_runtime.h>

// CoincidenceLIFBank: B=32 x T=4096 x D=256.
// Output layout (flattened tuple, float32):
//   [0, B*D) pooled | [B*D, +B*D*T) spikes | +D rw | +D tw | +D beta
//
// Numerics matched to XLA:GPU per-fusion emission:
//  - diagnostics + current-precompute fusions: classic elemental emitter,
//    UNcontracted mul/add; softplus log1p lowered as naive log(1+u).
//  - scan body (DUS-rooted Triton fusion): membrane update CONTRACTED:
//    m' = fma(beta, m, cur).  cur itself arrives materialized (uncontracted).
//  - logistic(x) = 1/(1+exp(-x)), IEEE divide.
//  - reset mp - s*1.0 exact; max(.,0) a no-op (all inputs >= 0).

#define NB 32
#define NT 4096
#define ND 256
#define THRESH 1.0f

__device__ __forceinline__ float softplus_xla(float x) {
    const float u = expf(-fabsf(x));
    return __fadd_rn(fmaxf(x, 0.0f), logf(__fadd_rn(1.0f, u)));
}

__device__ __forceinline__ float sigmoid_xla(float x) {
    return 1.0f / (__fadd_rn(1.0f, expf(-x)));
}

__global__ void __launch_bounds__(32)
lif_bank_kernel(const float* __restrict__ ref,
                const float* __restrict__ tgt,
                const int*   __restrict__ delays,
                const float* __restrict__ rw_raw,
                const float* __restrict__ tw_raw,
                const float* __restrict__ beta_raw,
                float* __restrict__ out)
{
    const int tid = blockIdx.x * 32 + threadIdx.x;   // 0..8191
    const int d = tid & (ND - 1);
    const int b = tid >> 8;

    // --- per-bank params: classic-emitter lowering, UNcontracted (bit-exact) ---
    const float rw   = softplus_xla(rw_raw[d]);
    const float tw   = softplus_xla(tw_raw[d]);
    const float beta = __fadd_rn(0.7f, __fmul_rn(0.295f, sigmoid_xla(beta_raw[d])));
    const int   delay = delays[d];
    const int   tmax  = NT - delay;   // t < tmax -> delayed ref valid, else 0

    const float* __restrict__ refrow = ref + b * NT + delay;
    const float* __restrict__ tgtrow = tgt + b * NT;

    float* out_pooled = out;
    float* out_spk    = out + NB * ND;
    float* out_rw     = out + NB * ND + (size_t)NB * ND * NT;
    float* out_tw     = out_rw + ND;
    float* out_beta   = out_tw + ND;

    float* __restrict__ spk = out_spk + (size_t)(b * ND + d) * NT;

    float m = 0.0f;
    float cnt = 0.0f;

    for (int t0 = 0; t0 < NT; t0 += 8) {
        // vectorized target loads (16B aligned, warp-uniform -> broadcast)
        const float4 tv0 = __ldg((const float4*)(tgtrow + t0));
        const float4 tv1 = __ldg((const float4*)(tgtrow + t0 + 4));
        float tv[8] = {tv0.x, tv0.y, tv0.z, tv0.w, tv1.x, tv1.y, tv1.z, tv1.w};

        float sp[8];
#pragma unroll
        for (int j = 0; j < 8; j++) {
            const int t = t0 + j;
            float rv = 0.0f;
            if (t < tmax) rv = __ldg(refrow + t);   // predicated load (OOB-safe)

            // current precompute fusion: UNCONTRACTED mul/mul/add
            const float cur = __fadd_rn(__fmul_rn(rw, rv), __fmul_rn(tw, tv[j]));
            // scan-body fusion (Triton): CONTRACTED membrane update
            const float mp = __fmaf_rn(beta, m, cur);
            // ms = mp-1 and p = (mp>=1) in parallel; chain closes on one FSEL.
            const float ms = __fadd_rn(mp, -THRESH);
            const bool  p  = (mp >= THRESH);
            m = p ? ms : mp;
            sp[j] = p ? 1.0f : 0.0f;
            cnt += sp[j];
        }
        // 32B full-sector store burst: two back-to-back STG.128
        *(float4*)(spk + t0)     = make_float4(sp[0], sp[1], sp[2], sp[3]);
        *(float4*)(spk + t0 + 4) = make_float4(sp[4], sp[5], sp[6], sp[7]);
    }

    // pooled = cnt / 4096 (exact)
    out_pooled[b * ND + d] = cnt * (1.0f / NT);

    if (b == 0) {
        out_rw[d]   = rw;
        out_tw[d]   = tw;
        out_beta[d] = beta;
    }
}

extern "C" void kernel_launch(void* const* d_in, const int* in_sizes, int n_in,
                              void* d_out, int out_size)
{
    const float* ref      = (const float*)d_in[0];
    const float* tgt      = (const float*)d_in[1];
    const int*   delays   = (const int*)  d_in[2];
    const float* rw_raw   = (const float*)d_in[3];
    const float* tw_raw   = (const float*)d_in[4];
    const float* beta_raw = (const float*)d_in[5];
    float* out = (float*)d_out;

    // 8192 independent (b,d) sequences; 1 thread each.
    // 256 blocks x 32 threads -> ~1-2 warps per SM, each on its own SMSP.
    lif_bank_kernel<<<(NB * ND) / 32, 32>>>(ref, tgt, delays, rw_raw, tw_raw,
                                            beta_raw, out);
}